// round 1
// baseline (speedup 1.0000x reference)
#include <cuda_runtime.h>
#include <math.h>

#define BATCH   64
#define IN_F    512
#define OUT_F   512
#define BASIS   8
#define KB      9            // 1 (silu/w slot) + BASIS
#define NSPLIT  19           // split-K over i
#define CHUNK   27           // ceil(512/19)
#define OTILE   64
#define STAGE_I 9
#define STAGE_KK (STAGE_I * KB)   // 81

// Scratch (allocation-free rule: __device__ globals)
__device__ float g_A[IN_F * KB * BATCH];            // A^T: [i*9+k][b], 1.18 MB
__device__ float g_part[NSPLIT * BATCH * OUT_F];    // split-K partials, 2.49 MB

// ---------------------------------------------------------------------------
// Kernel 1: augmented basis  A[(i*9+k)][b]
//   k=0: silu(x[b,i]);  k=1..8: T_k(clip(tanh(x[b,i])))  via Chebyshev recurrence
// ---------------------------------------------------------------------------
__global__ __launch_bounds__(256) void basis_kernel(const float* __restrict__ x) {
    int tid = blockIdx.x * blockDim.x + threadIdx.x;   // 32768 total
    int i = tid >> 6;          // feature index
    int b = tid & 63;          // batch index (fastest -> coalesced writes)
    float xv = x[b * IN_F + i];
    float t = tanhf(xv);
    t = fminf(fmaxf(t, -1.0f + 1e-6f), 1.0f - 1e-6f);
    float sig = 1.0f / (1.0f + expf(-xv));

    float* dst = g_A + i * (KB * BATCH) + b;
    dst[0 * BATCH] = xv * sig;     // silu slot
    dst[1 * BATCH] = t;            // T_1
    float tkm2 = 1.0f, tkm1 = t;
    #pragma unroll
    for (int k = 2; k <= BASIS; k++) {
        float tk = 2.0f * t * tkm1 - tkm2;
        dst[k * BATCH] = tk;
        tkm2 = tkm1; tkm1 = tk;
    }
}

// ---------------------------------------------------------------------------
// Kernel 2: out_partial[s] = A[64, ik-slice] @ CW[ik-slice, 64-o-tile]
//   CW[(i*9+0)][o] = w[i,o];  CW[(i*9+k)][o] = c[i,o,k-1] * w[i,o]
//   grid: (NSPLIT, OUT_F/OTILE), block 256 threads, 4x4 micro-tiles
// ---------------------------------------------------------------------------
__global__ __launch_bounds__(256) void gemm_kernel(const float* __restrict__ w,
                                                   const float* __restrict__ c) {
    __shared__ float As[STAGE_KK * BATCH];   // 81 x 64  (20.25 KB)
    __shared__ float Cs[STAGE_KK * OTILE];   // 81 x 64  (20.25 KB)

    const int s  = blockIdx.x;
    const int o0 = blockIdx.y * OTILE;
    const int ibeg = s * CHUNK;
    const int iend = min(ibeg + CHUNK, IN_F);
    const int tid = threadIdx.x;
    const int bb = tid & 15;    // 16 thread-groups along batch
    const int oo = tid >> 4;    // 16 thread-groups along out

    float acc[4][4] = {};

    for (int ist = ibeg; ist < iend; ist += STAGE_I) {
        const int ni = min(STAGE_I, iend - ist);

        // ---- stage A slab (contiguous copy) ----
        const float* gA = g_A + ist * (KB * BATCH);
        const int na = ni * KB * BATCH;                 // <= 5184
        for (int idx = tid; idx < na; idx += 256) As[idx] = gA[idx];

        // ---- stage CW slab: fuse c*w on the fly ----
        for (int p = tid; p < ni * OTILE; p += 256) {
            const int ii = p >> 6;
            const int oc = p & 63;
            const int i = ist + ii;
            const int o = o0 + oc;
            const float wv = w[i * OUT_F + o];
            const float4* cp = (const float4*)(c + ((size_t)(i * OUT_F + o)) * BASIS);
            const float4 c0 = cp[0];
            const float4 c1 = cp[1];
            float* cs = Cs + ii * (KB * OTILE) + oc;
            cs[0 * OTILE] = wv;
            cs[1 * OTILE] = c0.x * wv;
            cs[2 * OTILE] = c0.y * wv;
            cs[3 * OTILE] = c0.z * wv;
            cs[4 * OTILE] = c0.w * wv;
            cs[5 * OTILE] = c1.x * wv;
            cs[6 * OTILE] = c1.y * wv;
            cs[7 * OTILE] = c1.z * wv;
            cs[8 * OTILE] = c1.w * wv;
        }
        __syncthreads();

        // ---- compute ----
        for (int ii = 0; ii < ni; ii++) {
            #pragma unroll
            for (int k = 0; k < KB; k++) {
                const int kk = ii * KB + k;
                const float4 av = *(const float4*)&As[kk * BATCH + bb * 4];
                const float4 cv = *(const float4*)&Cs[kk * OTILE + oo * 4];
                acc[0][0] += av.x * cv.x; acc[0][1] += av.x * cv.y;
                acc[0][2] += av.x * cv.z; acc[0][3] += av.x * cv.w;
                acc[1][0] += av.y * cv.x; acc[1][1] += av.y * cv.y;
                acc[1][2] += av.y * cv.z; acc[1][3] += av.y * cv.w;
                acc[2][0] += av.z * cv.x; acc[2][1] += av.z * cv.y;
                acc[2][2] += av.z * cv.z; acc[2][3] += av.z * cv.w;
                acc[3][0] += av.w * cv.x; acc[3][1] += av.w * cv.y;
                acc[3][2] += av.w * cv.z; acc[3][3] += av.w * cv.w;
            }
        }
        __syncthreads();
    }

    // ---- write split-K partial ----
    float* pout = g_part + (size_t)s * (BATCH * OUT_F);
    #pragma unroll
    for (int r = 0; r < 4; r++) {
        const int b = bb * 4 + r;
        float4 v = make_float4(acc[r][0], acc[r][1], acc[r][2], acc[r][3]);
        *(float4*)&pout[b * OUT_F + o0 + oo * 4] = v;
    }
}

// ---------------------------------------------------------------------------
// Kernel 3: reduce split-K partials
// ---------------------------------------------------------------------------
__global__ __launch_bounds__(256) void reduce_kernel(float* __restrict__ out) {
    const int tid = blockIdx.x * blockDim.x + threadIdx.x;   // 32768
    float sum = 0.0f;
    #pragma unroll
    for (int s2 = 0; s2 < NSPLIT; s2++)
        sum += g_part[s2 * (BATCH * OUT_F) + tid];
    out[tid] = sum;
}

// ---------------------------------------------------------------------------
extern "C" void kernel_launch(void* const* d_in, const int* in_sizes, int n_in,
                              void* d_out, int out_size) {
    const float* x = (const float*)d_in[0];   // (64, 512)
    const float* w = (const float*)d_in[1];   // (512, 512)
    const float* c = (const float*)d_in[2];   // (512, 512, 8)
    float* out = (float*)d_out;               // (64, 512)

    basis_kernel<<<(BATCH * IN_F) / 256, 256>>>(x);
    gemm_kernel<<<dim3(NSPLIT, OUT_F / OTILE), 256>>>(w, c);
    reduce_kernel<<<(BATCH * OUT_F) / 256, 256>>>(out);
}

// round 4
// speedup vs baseline: 1.3545x; 1.3545x over previous
#include <cuda_runtime.h>
#include <math.h>

#define BATCH   64
#define IN_F    512
#define OUT_F   512
#define BASIS   8
#define KB      9                  // 1 (silu/w slot) + BASIS
#define NSPLIT  19                 // split-K over i
#define CHUNK   27                 // 19*27 = 513 -> 1 zero-pad i-row
#define IPAD    (NSPLIT * CHUNK)   // 513
#define STAGE_I 9
#define NSTAGE  3                  // 27 / 9
#define OTILE   64
#define STAGE_KK (STAGE_I * KB)    // 81

// Scratch (__device__ globals; pad rows of g_A stay .bss-zero forever)
__device__ float g_A[IPAD * KB * BATCH];
__device__ float g_part[NSPLIT * BATCH * OUT_F];

__device__ __forceinline__ unsigned long long dupf(float v) {
    unsigned int b = __float_as_uint(v);
    return ((unsigned long long)b << 32) | (unsigned long long)b;
}
__device__ __forceinline__ void ffma2(unsigned long long& d,
                                      unsigned long long a,
                                      unsigned long long b) {
    asm("fma.rn.f32x2 %0, %1, %2, %0;" : "+l"(d) : "l"(a), "l"(b));
}
__device__ __forceinline__ float pick(unsigned long long u, int hi) {
    return __uint_as_float(hi ? (unsigned int)(u >> 32) : (unsigned int)u);
}

// ---------------------------------------------------------------------------
// Kernel 1: augmented basis  A[(i*9+k)][b]
//   k=0: silu(x);  k=1..8: T_k(clip(tanh x)) via Chebyshev recurrence.
//   MUFU-only transcendentals.
// ---------------------------------------------------------------------------
__global__ __launch_bounds__(256) void basis_kernel(const float* __restrict__ x) {
    int g = blockIdx.x * 256 + threadIdx.x;    // 32768 threads
    int i = g >> 6;
    int b = g & 63;
    float xv = x[b * IN_F + i];

    float sig = __fdividef(1.0f, 1.0f + __expf(-xv));
    // tanh(x) = 1 - 2/(1 + e^{2x}); finite at both extremes
    float t = 1.0f - 2.0f * __fdividef(1.0f, 1.0f + __expf(2.0f * xv));
    t = fminf(fmaxf(t, -1.0f + 1e-6f), 1.0f - 1e-6f);

    float* dst = g_A + i * (KB * BATCH) + b;
    dst[0]     = xv * sig;   // silu slot (pairs with w)
    dst[BATCH] = t;          // T_1
    float tkm2 = 1.0f, tkm1 = t;
    #pragma unroll
    for (int k = 2; k <= BASIS; k++) {
        float tk = 2.0f * t * tkm1 - tkm2;
        dst[k * BATCH] = tk;
        tkm2 = tkm1; tkm1 = tk;
    }
}

// ---------------------------------------------------------------------------
// Kernel 2: split-K GEMM, f32x2-packed 4x4 micro-tiles, register-side dup.
//   grid (NSPLIT, 8) = 152 blocks (1 wave), 256 threads, 41.4 KB STATIC smem.
// ---------------------------------------------------------------------------
__global__ __launch_bounds__(256) void gemm_kernel(const float* __restrict__ w,
                                                   const float* __restrict__ c) {
    __shared__ float As[STAGE_KK * BATCH];   // [81][64] = 20736 B
    __shared__ float Cs[STAGE_KK * OTILE];   // [81][64] = 20736 B

    const int s   = blockIdx.x;
    const int o0  = blockIdx.y * OTILE;
    const int tid = threadIdx.x;
    const int bb4 = (tid & 15) * 4;
    const int oo4 = (tid >> 4) * 4;
    const int ibeg = s * CHUNK;

    float4 aReg[6];
    float  wReg[3];
    float4 cReg[3][2];

    unsigned long long acc[8];
    #pragma unroll
    for (int j = 0; j < 8; j++) acc[j] = 0ull;

    auto loadStage = [&](int istS) {
        const float4* srcA = (const float4*)(g_A + (size_t)istS * (KB * BATCH));
        #pragma unroll
        for (int j = 0; j < 6; j++) {
            int idx = tid + j * 256;
            aReg[j] = (idx < STAGE_KK * BATCH / 4) ? srcA[idx]
                                                   : make_float4(0.f, 0.f, 0.f, 0.f);
        }
        #pragma unroll
        for (int j = 0; j < 3; j++) {
            int p = tid + j * 256;
            if (p < STAGE_I * OTILE) {
                int ii = p >> 6, oc = p & 63;
                int i = istS + ii;
                int o = o0 + oc;
                if (i < IN_F) {
                    wReg[j] = w[i * OUT_F + o];
                    const float4* cp = (const float4*)(c + ((size_t)i * OUT_F + o) * BASIS);
                    cReg[j][0] = cp[0];
                    cReg[j][1] = cp[1];
                } else {
                    wReg[j] = 0.f;
                    cReg[j][0] = make_float4(0.f, 0.f, 0.f, 0.f);
                    cReg[j][1] = make_float4(0.f, 0.f, 0.f, 0.f);
                }
            }
        }
    };

    auto storeStage = [&]() {
        #pragma unroll
        for (int j = 0; j < 6; j++) {
            int idx = tid + j * 256;
            if (idx < STAGE_KK * BATCH / 4) ((float4*)As)[idx] = aReg[j];
        }
        #pragma unroll
        for (int j = 0; j < 3; j++) {
            int p = tid + j * 256;
            if (p < STAGE_I * OTILE) {
                int ii = p >> 6, oc = p & 63;
                float* cs = Cs + ii * (KB * OTILE) + oc;
                float wv = wReg[j];
                cs[0 * OTILE] = wv;
                cs[1 * OTILE] = cReg[j][0].x * wv;
                cs[2 * OTILE] = cReg[j][0].y * wv;
                cs[3 * OTILE] = cReg[j][0].z * wv;
                cs[4 * OTILE] = cReg[j][0].w * wv;
                cs[5 * OTILE] = cReg[j][1].x * wv;
                cs[6 * OTILE] = cReg[j][1].y * wv;
                cs[7 * OTILE] = cReg[j][1].z * wv;
                cs[8 * OTILE] = cReg[j][1].w * wv;
            }
        }
    };

    auto compute = [&]() {
        #pragma unroll
        for (int kk = 0; kk < STAGE_KK; kk++) {
            ulonglong2 a = *(const ulonglong2*)&As[kk * BATCH + bb4];  // (b0,b1),(b2,b3)
            float4 cv    = *(const float4*)&Cs[kk * OTILE + oo4];      // 4 o-values
            unsigned long long c0 = dupf(cv.x), c1 = dupf(cv.y);
            unsigned long long c2 = dupf(cv.z), c3 = dupf(cv.w);
            ffma2(acc[0], a.x, c0); ffma2(acc[1], a.x, c1);
            ffma2(acc[2], a.x, c2); ffma2(acc[3], a.x, c3);
            ffma2(acc[4], a.y, c0); ffma2(acc[5], a.y, c1);
            ffma2(acc[6], a.y, c2); ffma2(acc[7], a.y, c3);
        }
    };

    // Software pipeline: STS current, sync, prefetch next G->R, compute, sync.
    loadStage(ibeg);
    #pragma unroll
    for (int st = 0; st < NSTAGE; st++) {
        storeStage();
        __syncthreads();
        if (st < NSTAGE - 1) loadStage(ibeg + (st + 1) * STAGE_I);
        compute();
        __syncthreads();
    }

    // Write split-K partial (float4 rows)
    float* pout = g_part + (size_t)s * (BATCH * OUT_F);
    #pragma unroll
    for (int r = 0; r < 4; r++) {
        const int b = bb4 + r;
        const int p = r >> 1;
        const int hi = r & 1;
        float4 v;
        v.x = pick(acc[p * 4 + 0], hi);
        v.y = pick(acc[p * 4 + 1], hi);
        v.z = pick(acc[p * 4 + 2], hi);
        v.w = pick(acc[p * 4 + 3], hi);
        *(float4*)&pout[b * OUT_F + o0 + oo4] = v;
    }
}

// ---------------------------------------------------------------------------
// Kernel 3: reduce split-K partials (float4, deterministic)
// ---------------------------------------------------------------------------
__global__ __launch_bounds__(256) void reduce_kernel(float* __restrict__ out) {
    int t = blockIdx.x * 256 + threadIdx.x;   // 8192
    const float4* gp = (const float4*)g_part;
    float4 sum = gp[t];
    #pragma unroll
    for (int k = 1; k < NSPLIT; k++) {
        float4 v = gp[k * (BATCH * OUT_F / 4) + t];
        sum.x += v.x; sum.y += v.y; sum.z += v.z; sum.w += v.w;
    }
    ((float4*)out)[t] = sum;
}

// ---------------------------------------------------------------------------
extern "C" void kernel_launch(void* const* d_in, const int* in_sizes, int n_in,
                              void* d_out, int out_size) {
    const float* x = (const float*)d_in[0];   // (64, 512)
    const float* w = (const float*)d_in[1];   // (512, 512)
    const float* c = (const float*)d_in[2];   // (512, 512, 8)
    float* out = (float*)d_out;               // (64, 512)

    basis_kernel<<<(BATCH * IN_F) / 256, 256>>>(x);
    gemm_kernel<<<dim3(NSPLIT, OUT_F / OTILE), 256>>>(w, c);
    reduce_kernel<<<(BATCH * OUT_F) / 4 / 256, 256>>>(out);
}